// round 12
// baseline (speedup 1.0000x reference)
#include <cuda_runtime.h>

typedef unsigned long long ull;

#define THREADS 256
#define PAD     66
#define SCALE_F 0.125f
#define FULLM   0xffffffffu

// smem float offsets (stride 66 everywhere: conflict-free LDS.64 in gemm)
#define QSM 0
#define KSM 4224
#define LGT 8448
#define TOT 12672
#define SMEM_FLOATS (TOT + 256)
#define SMEM_BYTES  (SMEM_FLOATS * 4)   // 51712 B -> 3 CTAs/SM (reg-limited)

__device__ __forceinline__ ull fma2(ull a, ull b, ull c) {
    ull d;
    asm("fma.rn.f32x2 %0, %1, %2, %3;" : "=l"(d) : "l"(a), "l"(b), "l"(c));
    return d;
}
__device__ __forceinline__ float hsum2(ull a) {
    unsigned lo, hi;
    asm("mov.b64 {%0, %1}, %2;" : "=r"(lo), "=r"(hi) : "l"(a));
    return __uint_as_float(lo) + __uint_as_float(hi);
}
__device__ __forceinline__ float sigm(float x) {
    return __fdividef(1.0f, 1.0f + __expf(-x));
}

// 64x64 row-major gmem tile -> smem [64][PAD] (float2 stores: PAD=66 is 8B-aligned)
__device__ __forceinline__ void load64(const float* __restrict__ src, float* dst, int tid) {
    #pragma unroll
    for (int r = 0; r < 4; ++r) {
        int f   = tid + r * THREADS;
        int row = f >> 4;
        int dp  = (f & 15) * 4;
        float4 v = ((const float4*)src)[f];
        float* p = dst + row * PAD + dp;
        *(float2*)p       = make_float2(v.x, v.y);
        *(float2*)(p + 2) = make_float2(v.z, v.w);
    }
}

__global__ void __launch_bounds__(THREADS, 3)
cope_kernel(const float* __restrict__ q, const float* __restrict__ kmat,
            const float* __restrict__ pe, const int* __restrict__ flagp,
            float* __restrict__ out)
{
    extern __shared__ float sm[];
    float* qsm = sm + QSM;
    float* ksm = sm + KSM;     // pe^T in prologue, k tiles in loop
    float* lgt = sm + LGT;
    float* tot = sm + TOT;     // [64 rows][4 quarter-totals]

    const int tid  = threadIdx.x;
    const int w    = tid >> 5;
    const int lane = tid & 31;
    const int rh   = w >> 2;           // row half
    const int kq   = w & 3;            // key quarter
    const int j4   = lane & 3;
    const int row0 = rh * 32 + (lane >> 2) * 4;
    const int key0 = kq * 16 + j4 * 4;
    const int b    = blockIdx.x >> 4;
    const int rb   = blockIdx.x & 15;
    const int rowg0 = b * 1024 + rb * 64;
    const float* kb = kmat + b * 65536;
    const int flag = *flagp;

    // ---- prologue: pe^T -> ksm; base rows -> qsm
    for (int i = tid; i < 4096; i += THREADS) {     // pe[d][n] -> ksm[n][d]
        int d = i >> 6, n = i & 63;
        ksm[n * PAD + d] = pe[i];
    }
    load64((flag ? q : kmat) + rowg0 * 64, qsm, tid);
    __syncthreads();

    // ---- logits_int gemm: lgt[row][n] = base[row]·pe[:,n]
    {
        ull acc[4][4];
        #pragma unroll
        for (int i = 0; i < 4; ++i)
            #pragma unroll
            for (int j = 0; j < 4; ++j) acc[i][j] = 0ull;
        #pragma unroll 8
        for (int d = 0; d < 64; d += 2) {
            ull qv[4], kv[4];
            #pragma unroll
            for (int i = 0; i < 4; ++i) qv[i] = *(const ull*)(qsm + (row0 + i) * PAD + d);
            #pragma unroll
            for (int j = 0; j < 4; ++j) kv[j] = *(const ull*)(ksm + (key0 + j) * PAD + d);
            #pragma unroll
            for (int i = 0; i < 4; ++i)
                #pragma unroll
                for (int j = 0; j < 4; ++j)
                    acc[i][j] = fma2(qv[i], kv[j], acc[i][j]);
        }
        #pragma unroll
        for (int i = 0; i < 4; ++i) {
            float* p = lgt + (row0 + i) * PAD + key0;
            *(float2*)p       = make_float2(hsum2(acc[i][0]), hsum2(acc[i][1]));
            *(float2*)(p + 2) = make_float2(hsum2(acc[i][2]), hsum2(acc[i][3]));
        }
    }
    if (tid < 64) lgt[tid * PAD + 64] = 0.0f;       // guard: pos==63 -> w=0 exact
    __syncthreads();

    if (!flag) load64(q + rowg0 * 64, qsm, tid);    // gates always use q
    {   // k tile 15 -> ksm (sync)
        const float4* src = (const float4*)(kb + 15 * 4096);
        float4 kr[4];
        #pragma unroll
        for (int r = 0; r < 4; ++r) kr[r] = src[tid + r * THREADS];
        #pragma unroll
        for (int r = 0; r < 4; ++r) {
            int f = tid + r * THREADS;
            float* p = ksm + (f >> 4) * PAD + (f & 15) * 4;
            *(float2*)p       = make_float2(kr[r].x, kr[r].y);
            *(float2*)(p + 2) = make_float2(kr[r].z, kr[r].w);
        }
    }
    __syncthreads();

    // ---- tile loop: gemm + fused hierarchical suffix-scan; 2 barriers/tile
    float cl[4] = {0.0f, 0.0f, 0.0f, 0.0f};        // carries for my 4 frag rows
    int kend = 0;

    for (int T = 15; ; --T) {
        // gate gemm on ksm
        ull acc[4][4];
        #pragma unroll
        for (int i = 0; i < 4; ++i)
            #pragma unroll
            for (int j = 0; j < 4; ++j) acc[i][j] = 0ull;
        #pragma unroll 8
        for (int d = 0; d < 64; d += 2) {
            ull qv[4], kv[4];
            #pragma unroll
            for (int i = 0; i < 4; ++i) qv[i] = *(const ull*)(qsm + (row0 + i) * PAD + d);
            #pragma unroll
            for (int j = 0; j < 4; ++j) kv[j] = *(const ull*)(ksm + (key0 + j) * PAD + d);
            #pragma unroll
            for (int i = 0; i < 4; ++i)
                #pragma unroll
                for (int j = 0; j < 4; ++j)
                    acc[i][j] = fma2(qv[i], kv[j], acc[i][j]);
        }

        // epilogue: sigmoid + local suffix (within my 4 keys) + quad suffix (width-4 shfl)
        float suf[4][4], I[4], excl[4];
        #pragma unroll
        for (int i = 0; i < 4; ++i) {
            float g0 = sigm(hsum2(acc[i][0]) * SCALE_F);
            float g1 = sigm(hsum2(acc[i][1]) * SCALE_F);
            float g2 = sigm(hsum2(acc[i][2]) * SCALE_F);
            float g3 = sigm(hsum2(acc[i][3]) * SCALE_F);
            suf[i][3] = g3;
            suf[i][2] = g3 + g2;
            suf[i][1] = suf[i][2] + g1;
            suf[i][0] = suf[i][1] + g0;
            I[i] = suf[i][0];
        }
        #pragma unroll
        for (int i = 0; i < 4; ++i) {
            float u = __shfl_down_sync(FULLM, I[i], 1, 4);
            if (j4 < 3) I[i] += u;
        }
        #pragma unroll
        for (int i = 0; i < 4; ++i) {
            float u = __shfl_down_sync(FULLM, I[i], 2, 4);
            if (j4 < 2) I[i] += u;
        }
        #pragma unroll
        for (int i = 0; i < 4; ++i) excl[i] = I[i] - suf[i][0];
        if (j4 == 0) {
            #pragma unroll
            for (int i = 0; i < 4; ++i) tot[(row0 + i) * 4 + kq] = I[i];   // quarter total
        }

        // early LDG of next k tile (hidden under gather phase)
        float4 kr[4];
        if (T > 0) {
            const float4* src = (const float4*)(kb + (T - 1) * 4096);
            #pragma unroll
            for (int r = 0; r < 4; ++r) kr[r] = src[tid + r * THREADS];
        }
        __syncthreads();                           // totals visible

        // gather + emit; carries replicate bit-identically across the 4 quarter warps
        bool sat = true;
        #pragma unroll
        for (int i = 0; i < 4; ++i) {
            int r = row0 + i;
            float t0 = tot[r * 4 + 0], t1 = tot[r * 4 + 1];
            float t2 = tot[r * 4 + 2], t3 = tot[r * 4 + 3];
            float hiq = (kq == 0) ? t1 + t2 + t3
                      : (kq == 1) ? t2 + t3
                      : (kq == 2) ? t3 : 0.0f;
            float basec = cl[i] + hiq + excl[i];
            const float* lr = lgt + r * PAD;
            float o[4];
            #pragma unroll
            for (int e = 0; e < 4; ++e) {
                float pos = fminf(basec + suf[i][e], 63.0f);
                float pf  = floorf(pos);
                int   ip  = (int)pf;
                float wt  = pos - pf;
                o[e] = lr[ip + 1] * wt + lr[ip] * (1.0f - wt);
            }
            __stcs((float4*)(out + (rowg0 + r) * 1024 + T * 64 + key0),
                   make_float4(o[0], o[1], o[2], o[3]));
            cl[i] += ((t0 + t1) + t2) + t3;        // fixed order -> identical in all warps
            sat = sat && (cl[i] >= 63.0f);
        }

        if (T > 0) {                               // stage next k tile into ksm
            #pragma unroll
            for (int r = 0; r < 4; ++r) {
                int f = tid + r * THREADS;
                float* p = ksm + (f >> 4) * PAD + (f & 15) * 4;
                *(float2*)p       = make_float2(kr[r].x, kr[r].y);
                *(float2*)(p + 2) = make_float2(kr[r].z, kr[r].w);
            }
        }
        bool alldone = __syncthreads_and(sat);     // vote; publishes ksm + guards tot reuse
        if (alldone) { kend = T * 64; break; }
        if (T == 0)  break;
    }

    // ---- saturated bulk fill: keys [0, kend) = logits_int[row][63]
    if (kend > 0) {
        #pragma unroll
        for (int rr = 0; rr < 8; ++rr) {
            int r = w * 8 + rr;
            float v = lgt[r * PAD + 63];
            float4 vv = make_float4(v, v, v, v);
            float* dst = out + (rowg0 + r) * 1024;
            for (int c = 4 * lane; c < kend; c += 128)
                __stcs((float4*)(dst + c), vv);
        }
    }
}

extern "C" void kernel_launch(void* const* d_in, const int* in_sizes, int n_in,
                              void* d_out, int out_size) {
    const float* q    = (const float*)d_in[0];
    const float* k    = (const float*)d_in[1];
    // d_in[2] = v (unused in mode 0)
    const float* pe   = (const float*)d_in[3];
    // d_in[4] = w_k (unused)
    const int*   flag = (const int*)d_in[5];
    float* out = (float*)d_out;

    cudaFuncSetAttribute(cope_kernel, cudaFuncAttributeMaxDynamicSharedMemorySize, SMEM_BYTES);
    const int grid = 32 * 16;   // 512 CTAs: 32 batches x 16 row-blocks of 64
    cope_kernel<<<grid, THREADS, SMEM_BYTES>>>(q, k, pe, flag, out);
}

// round 14
// speedup vs baseline: 1.6015x; 1.6015x over previous
#include <cuda_runtime.h>

typedef unsigned long long ull;

#define THREADS 256
#define SCALE_F 0.125f
#define FULLM   0xffffffffu
#define PAD     66

// smem float offsets
#define QSM 0
#define KSM (64 * PAD)          // 4224
#define GSM (2 * 64 * PAD)      // 8448  (pe^T in prologue, gate tiles in loop)
#define LGT (3 * 64 * PAD)      // 12672
#define SMEM_FLOATS (4 * 64 * PAD)
#define SMEM_BYTES  (SMEM_FLOATS * 4)   // 67584 B -> 3 CTAs/SM

__device__ __forceinline__ ull fma2(ull a, ull b, ull c) {
    ull d;
    asm("fma.rn.f32x2 %0, %1, %2, %3;" : "=l"(d) : "l"(a), "l"(b), "l"(c));
    return d;
}
__device__ __forceinline__ float hsum2(ull a) {
    unsigned lo, hi;
    asm("mov.b64 {%0, %1}, %2;" : "=r"(lo), "=r"(hi) : "l"(a));
    return __uint_as_float(lo) + __uint_as_float(hi);
}
__device__ __forceinline__ float sigm(float x) {
    return __fdividef(1.0f, 1.0f + __expf(-x));
}

// synchronous 64x64 row-major tile load into smem [64][PAD]
__device__ __forceinline__ void load64(const float* __restrict__ src, float* dst, int tid) {
    #pragma unroll
    for (int r = 0; r < 4; ++r) {
        int f   = tid + r * THREADS;
        int row = f >> 4;
        int dp  = (f & 15) * 4;
        float4 v = ((const float4*)src)[f];
        float* p = dst + row * PAD + dp;
        *(float2*)p       = make_float2(v.x, v.y);
        *(float2*)(p + 2) = make_float2(v.z, v.w);
    }
}

// 64x64x64 register-tiled GEMM: dst[row][key] = qs[row]·ks[key]  (+sigmoid if GATE)
template <bool GATE>
__device__ __forceinline__ void gemm64(const float* qs, const float* ks, float* dst,
                                       int lane, int w)
{
    const int row0 = (w >> 2) * 32 + (lane >> 2) * 4;
    const int key0 = (w & 3) * 16 + (lane & 3) * 4;
    ull acc[4][4];
    #pragma unroll
    for (int i = 0; i < 4; ++i)
        #pragma unroll
        for (int j = 0; j < 4; ++j) acc[i][j] = 0ull;

    #pragma unroll 8
    for (int d = 0; d < 64; d += 2) {
        ull qv[4], kv[4];
        #pragma unroll
        for (int i = 0; i < 4; ++i) qv[i] = *(const ull*)(qs + (row0 + i) * PAD + d);
        #pragma unroll
        for (int j = 0; j < 4; ++j) kv[j] = *(const ull*)(ks + (key0 + j) * PAD + d);
        #pragma unroll
        for (int i = 0; i < 4; ++i)
            #pragma unroll
            for (int j = 0; j < 4; ++j)
                acc[i][j] = fma2(qv[i], kv[j], acc[i][j]);
    }
    #pragma unroll
    for (int i = 0; i < 4; ++i) {
        float v0 = hsum2(acc[i][0]), v1 = hsum2(acc[i][1]);
        float v2 = hsum2(acc[i][2]), v3 = hsum2(acc[i][3]);
        if (GATE) {
            v0 = sigm(v0 * SCALE_F); v1 = sigm(v1 * SCALE_F);
            v2 = sigm(v2 * SCALE_F); v3 = sigm(v3 * SCALE_F);
        }
        float* p = dst + (row0 + i) * PAD + key0;
        *(float2*)p       = make_float2(v0, v1);
        *(float2*)(p + 2) = make_float2(v2, v3);
    }
}

__global__ void __launch_bounds__(THREADS, 3)
cope_kernel(const float* __restrict__ q, const float* __restrict__ kmat,
            const float* __restrict__ pe, const int* __restrict__ flagp,
            float* __restrict__ out)
{
    extern __shared__ float sm[];
    float* qsm = sm + QSM;
    float* ksm = sm + KSM;
    float* gsm = sm + GSM;       // pe^T in prologue, gate tiles in loop
    float* lgt = sm + LGT;

    const int tid  = threadIdx.x;
    const int w    = tid >> 5;
    const int lane = tid & 31;
    const int b    = blockIdx.x >> 4;
    const int rb   = blockIdx.x & 15;
    const int rowg0 = b * 1024 + rb * 64;
    const float* kb = kmat + b * 65536;
    const int flag = *flagp;

    // ---- prologue: pe^T -> gsm; base rows -> qsm
    for (int i = tid; i < 4096; i += THREADS) {       // pe[d][n] -> gsm[n][d]
        int d = i >> 6, n = i & 63;
        gsm[n * PAD + d] = pe[i];
    }
    load64((flag ? q : kmat) + rowg0 * 64, qsm, tid);
    __syncthreads();

    gemm64<false>(qsm, gsm, lgt, lane, w);            // logits_int table
    __syncthreads();
    if (tid < 64) lgt[tid * PAD + 64] = 0.0f;         // guard: pos==63 -> w=0 exact
    if (!flag) load64(q + rowg0 * 64, qsm, tid);      // gates always use q
    load64(kb + 15 * 4096, ksm, tid);                 // k tile 15
    __syncthreads();                                  // ksm(t15), lgt, qsm visible

    // ---- tile loop: gemm -> barrier -> LDG(next) -> scan -> STS(next) -> vote
    float cl[8];
    #pragma unroll
    for (int rr = 0; rr < 8; ++rr) cl[rr] = 0.0f;

    int kend = 0;
    for (int T = 15; ; --T) {
        gemm64<true>(qsm, ksm, gsm, lane, w);         // sigmoid gates into gsm
        __syncthreads();                              // gsm ready; ksm reads done

        // early LDG of next k tile into registers (latency hidden by the scan)
        float4 kr[4];
        if (T > 0) {
            const float4* src = (const float4*)(kb + (T - 1) * 4096);
            #pragma unroll
            for (int r = 0; r < 4; ++r) kr[r] = src[tid + r * THREADS];
        }

        // scan: warp w owns rows w*8..w*8+7; two 32-key chunks, high first
        #pragma unroll
        for (int c = 1; c >= 0; --c) {
            float s[8];
            #pragma unroll
            for (int rr = 0; rr < 8; ++rr)
                s[rr] = gsm[(w * 8 + rr) * PAD + c * 32 + lane];
            #pragma unroll
            for (int off = 1; off < 32; off <<= 1) {
                #pragma unroll
                for (int rr = 0; rr < 8; ++rr) {
                    float u = __shfl_down_sync(FULLM, s[rr], off);
                    if (lane + off < 32) s[rr] += u;
                }
            }
            #pragma unroll
            for (int rr = 0; rr < 8; ++rr) {
                float pos = fminf(cl[rr] + s[rr], 63.0f);
                float pf  = floorf(pos);
                int   ip  = (int)pf;
                float wt  = pos - pf;
                const float* lr = lgt + (w * 8 + rr) * PAD;
                float val = lr[ip + 1] * wt + lr[ip] * (1.0f - wt);
                __stcs(out + (rowg0 + w * 8 + rr) * 1024 + T * 64 + c * 32 + lane, val);
            }
            #pragma unroll
            for (int rr = 0; rr < 8; ++rr)
                cl[rr] += __shfl_sync(FULLM, s[rr], 0);
        }

        // stage next k tile into ksm (reads of old ksm finished at barrier above)
        if (T > 0) {
            #pragma unroll
            for (int r = 0; r < 4; ++r) {
                int f = tid + r * THREADS;
                float* p = ksm + (f >> 4) * PAD + (f & 15) * 4;
                *(float2*)p       = make_float2(kr[r].x, kr[r].y);
                *(float2*)(p + 2) = make_float2(kr[r].z, kr[r].w);
            }
        }

        bool sat = true;
        #pragma unroll
        for (int rr = 0; rr < 8; ++rr) sat = sat && (cl[rr] >= 63.0f);
        bool alldone = __syncthreads_and(sat);        // publishes ksm; frees gsm
        if (alldone) { kend = T * 64; break; }
        if (T == 0)  break;
    }

    // ---- saturated bulk fill: keys [0, kend) = logits_int[row][63]
    if (kend > 0) {
        #pragma unroll
        for (int rr = 0; rr < 8; ++rr) {
            int r = w * 8 + rr;
            float v = lgt[r * PAD + 63];
            float4 vv = make_float4(v, v, v, v);
            float* dst = out + (rowg0 + r) * 1024;
            for (int c = 4 * lane; c < kend; c += 128)
                __stcs((float4*)(dst + c), vv);
        }
    }
}

extern "C" void kernel_launch(void* const* d_in, const int* in_sizes, int n_in,
                              void* d_out, int out_size) {
    const float* q    = (const float*)d_in[0];
    const float* k    = (const float*)d_in[1];
    // d_in[2] = v (unused in mode 0)
    const float* pe   = (const float*)d_in[3];
    // d_in[4] = w_k (unused)
    const int*   flag = (const int*)d_in[5];
    float* out = (float*)d_out;

    cudaFuncSetAttribute(cope_kernel, cudaFuncAttributeMaxDynamicSharedMemorySize, SMEM_BYTES);
    const int grid = 32 * 16;   // 512 CTAs: 32 batches x 16 row-blocks of 64
    cope_kernel<<<grid, THREADS, SMEM_BYTES>>>(q, k, pe, flag, out);
}

// round 15
// speedup vs baseline: 1.6120x; 1.0065x over previous
#include <cuda_runtime.h>

typedef unsigned long long ull;

#define THREADS 256
#define SCALE_F 0.125f
#define FULLM   0xffffffffu
#define PAD     66

// smem float offsets
#define QSM 0
#define KSM (64 * PAD)          // 4224
#define GSM (2 * 64 * PAD)      // 8448  (pe^T in prologue, gate tiles in loop)
#define LGT (3 * 64 * PAD)      // 12672
#define SMEM_FLOATS (4 * 64 * PAD)
#define SMEM_BYTES  (SMEM_FLOATS * 4)   // 67584 B -> 3 CTAs/SM

__device__ __forceinline__ ull fma2(ull a, ull b, ull c) {
    ull d;
    asm("fma.rn.f32x2 %0, %1, %2, %3;" : "=l"(d) : "l"(a), "l"(b), "l"(c));
    return d;
}
__device__ __forceinline__ float hsum2(ull a) {
    unsigned lo, hi;
    asm("mov.b64 {%0, %1}, %2;" : "=r"(lo), "=r"(hi) : "l"(a));
    return __uint_as_float(lo) + __uint_as_float(hi);
}
__device__ __forceinline__ float sigm(float x) {
    return __fdividef(1.0f, 1.0f + __expf(-x));
}

// synchronous 64x64 row-major tile load into smem [64][PAD]
__device__ __forceinline__ void load64(const float* __restrict__ src, float* dst, int tid) {
    #pragma unroll
    for (int r = 0; r < 4; ++r) {
        int f   = tid + r * THREADS;
        int row = f >> 4;
        int dp  = (f & 15) * 4;
        float4 v = ((const float4*)src)[f];
        float* p = dst + row * PAD + dp;
        *(float2*)p       = make_float2(v.x, v.y);
        *(float2*)(p + 2) = make_float2(v.z, v.w);
    }
}

// 64x64x64 register-tiled GEMM: dst[row][key] = qs[row]·ks[key]  (+sigmoid if GATE)
// Frag rows are STRIDED: thread (w,lane) owns rows (w>>2)*32 + (lane>>2) + {0,8,16,24}.
// 8 distinct qv addresses/warp -> banks 2g mod 32 (g=0..7): conflict-free LDS.64.
template <bool GATE>
__device__ __forceinline__ void gemm64(const float* qs, const float* ks, float* dst,
                                       int lane, int w)
{
    const int rowb = (w >> 2) * 32 + (lane >> 2);    // + i*8, i=0..3
    const int key0 = (w & 3) * 16 + (lane & 3) * 4;
    ull acc[4][4];
    #pragma unroll
    for (int i = 0; i < 4; ++i)
        #pragma unroll
        for (int j = 0; j < 4; ++j) acc[i][j] = 0ull;

    #pragma unroll 8
    for (int d = 0; d < 64; d += 2) {
        ull qv[4], kv[4];
        #pragma unroll
        for (int i = 0; i < 4; ++i) qv[i] = *(const ull*)(qs + (rowb + i * 8) * PAD + d);
        #pragma unroll
        for (int j = 0; j < 4; ++j) kv[j] = *(const ull*)(ks + (key0 + j) * PAD + d);
        #pragma unroll
        for (int i = 0; i < 4; ++i)
            #pragma unroll
            for (int j = 0; j < 4; ++j)
                acc[i][j] = fma2(qv[i], kv[j], acc[i][j]);
    }
    #pragma unroll
    for (int i = 0; i < 4; ++i) {
        float v0 = hsum2(acc[i][0]), v1 = hsum2(acc[i][1]);
        float v2 = hsum2(acc[i][2]), v3 = hsum2(acc[i][3]);
        if (GATE) {
            v0 = sigm(v0 * SCALE_F); v1 = sigm(v1 * SCALE_F);
            v2 = sigm(v2 * SCALE_F); v3 = sigm(v3 * SCALE_F);
        }
        float* p = dst + (rowb + i * 8) * PAD + key0;
        *(float2*)p       = make_float2(v0, v1);
        *(float2*)(p + 2) = make_float2(v2, v3);
    }
}

__global__ void __launch_bounds__(THREADS, 3)
cope_kernel(const float* __restrict__ q, const float* __restrict__ kmat,
            const float* __restrict__ pe, const int* __restrict__ flagp,
            float* __restrict__ out)
{
    extern __shared__ float sm[];
    float* qsm = sm + QSM;
    float* ksm = sm + KSM;
    float* gsm = sm + GSM;       // pe^T in prologue, gate tiles in loop
    float* lgt = sm + LGT;

    const int tid  = threadIdx.x;
    const int w    = tid >> 5;
    const int lane = tid & 31;
    const int b    = blockIdx.x >> 4;
    const int rb   = blockIdx.x & 15;
    const int rowg0 = b * 1024 + rb * 64;
    const float* kb = kmat + b * 65536;
    const int flag = *flagp;

    // ---- prologue: pe^T -> gsm; base rows -> qsm
    for (int i = tid; i < 4096; i += THREADS) {       // pe[d][n] -> gsm[n][d]
        int d = i >> 6, n = i & 63;
        gsm[n * PAD + d] = pe[i];
    }
    load64((flag ? q : kmat) + rowg0 * 64, qsm, tid);
    __syncthreads();

    gemm64<false>(qsm, gsm, lgt, lane, w);            // logits_int table
    __syncthreads();
    if (tid < 64) lgt[tid * PAD + 64] = 0.0f;         // guard: pos==63 -> w=0 exact
    if (!flag) load64(q + rowg0 * 64, qsm, tid);      // gates always use q
    load64(kb + 15 * 4096, ksm, tid);                 // k tile 15
    __syncthreads();                                  // ksm(t15), lgt, qsm visible

    // ---- tile loop: gemm -> barrier -> LDG(next) -> scan -> STS(next) -> vote
    float cl[8];
    #pragma unroll
    for (int rr = 0; rr < 8; ++rr) cl[rr] = 0.0f;

    int kend = 0;
    for (int T = 15; ; --T) {
        gemm64<true>(qsm, ksm, gsm, lane, w);         // sigmoid gates into gsm
        __syncthreads();                              // gsm ready; ksm reads done

        // early LDG of next k tile into registers (latency hidden by the scan)
        float4 kr[4];
        if (T > 0) {
            const float4* src = (const float4*)(kb + (T - 1) * 4096);
            #pragma unroll
            for (int r = 0; r < 4; ++r) kr[r] = src[tid + r * THREADS];
        }

        // scan: warp w owns rows w*8..w*8+7; two 32-key chunks, high first
        #pragma unroll
        for (int c = 1; c >= 0; --c) {
            float s[8];
            #pragma unroll
            for (int rr = 0; rr < 8; ++rr)
                s[rr] = gsm[(w * 8 + rr) * PAD + c * 32 + lane];
            #pragma unroll
            for (int off = 1; off < 32; off <<= 1) {
                #pragma unroll
                for (int rr = 0; rr < 8; ++rr) {
                    float u = __shfl_down_sync(FULLM, s[rr], off);
                    if (lane + off < 32) s[rr] += u;
                }
            }
            #pragma unroll
            for (int rr = 0; rr < 8; ++rr) {
                float pos = fminf(cl[rr] + s[rr], 63.0f);
                float pf  = floorf(pos);
                int   ip  = (int)pf;
                float wt  = pos - pf;
                const float* lr = lgt + (w * 8 + rr) * PAD;
                float val = lr[ip + 1] * wt + lr[ip] * (1.0f - wt);
                __stcs(out + (rowg0 + w * 8 + rr) * 1024 + T * 64 + c * 32 + lane, val);
            }
            #pragma unroll
            for (int rr = 0; rr < 8; ++rr)
                cl[rr] += __shfl_sync(FULLM, s[rr], 0);
        }

        // stage next k tile into ksm (reads of old ksm finished at barrier above)
        if (T > 0) {
            #pragma unroll
            for (int r = 0; r < 4; ++r) {
                int f = tid + r * THREADS;
                float* p = ksm + (f >> 4) * PAD + (f & 15) * 4;
                *(float2*)p       = make_float2(kr[r].x, kr[r].y);
                *(float2*)(p + 2) = make_float2(kr[r].z, kr[r].w);
            }
        }

        bool sat = true;
        #pragma unroll
        for (int rr = 0; rr < 8; ++rr) sat = sat && (cl[rr] >= 63.0f);
        bool alldone = __syncthreads_and(sat);        // publishes ksm; frees gsm
        if (alldone) { kend = T * 64; break; }
        if (T == 0)  break;
    }

    // ---- saturated bulk fill: keys [0, kend) = logits_int[row][63]
    if (kend > 0) {
        #pragma unroll
        for (int rr = 0; rr < 8; ++rr) {
            int r = w * 8 + rr;
            float v = lgt[r * PAD + 63];
            float4 vv = make_float4(v, v, v, v);
            float* dst = out + (rowg0 + r) * 1024;
            for (int c = 4 * lane; c < kend; c += 128)
                __stcs((float4*)(dst + c), vv);
        }
    }
}

extern "C" void kernel_launch(void* const* d_in, const int* in_sizes, int n_in,
                              void* d_out, int out_size) {
    const float* q    = (const float*)d_in[0];
    const float* k    = (const float*)d_in[1];
    // d_in[2] = v (unused in mode 0)
    const float* pe   = (const float*)d_in[3];
    // d_in[4] = w_k (unused)
    const int*   flag = (const int*)d_in[5];
    float* out = (float*)d_out;

    cudaFuncSetAttribute(cope_kernel, cudaFuncAttributeMaxDynamicSharedMemorySize, SMEM_BYTES);
    const int grid = 32 * 16;   // 512 CTAs: 32 batches x 16 row-blocks of 64
    cope_kernel<<<grid, THREADS, SMEM_BYTES>>>(q, k, pe, flag, out);
}